// round 3
// baseline (speedup 1.0000x reference)
#include <cuda_runtime.h>

#define NB   256
#define NT   1024
#define NS   7
#define NH   64
#define NL   4
#define NOUT 3

#define CH   64                 // x-staging chunk length (timesteps)
#define XPC  (CH * NS)          // 448 floats per chunk
#define TBLH_FLOATS (3 * 16 * 16 * 64)  // 49152 floats = 192 KB
#define TBLO_FLOATS (16 * 16 * 4)       // 1024 floats  = 4 KB
#define SMEM_BYTES  ((TBLH_FLOATS + TBLO_FLOATS + 2 * XPC) * 4)  // 204288 B

// One warp per batch element. Lane owns neurons (lane, lane+32).
// Spikes exchanged via ballot (64-bit mask, warp-uniform) -> ZERO barriers in
// the time loop. Hidden matvec = 16 LUT lookups of 4-bit subset-sums.
__global__ __launch_bounds__(64, 1)
void snn_kernel(const float* __restrict__ x,
                const float* __restrict__ hidden0,
                const float* __restrict__ w1,
                const float* __restrict__ b1,
                const float* __restrict__ w_h,
                const float* __restrict__ b_h,
                const float* __restrict__ w_out,
                const float* __restrict__ b_out,
                float* __restrict__ out_outputs,   // (B,T,OUT)
                float* __restrict__ out_hidden)    // (B,T,L,H)
{
    extern __shared__ float smem[];
    float* tblH = smem;                       // [3][16][16][64] : (l,q,p) -> float2 per lane
    float* tblO = smem + TBLH_FLOATS;         // [16][16][4]     : (q,p)   -> 3 outs (pad 4)
    float* xbuf = tblO + TBLO_FLOATS;         // [2][XPC]

    const int tid  = threadIdx.x;
    const int lane = tid & 31;
    const int wid  = tid >> 5;

    // ---- build 4-bit subset-sum LUTs (64 threads cooperate) ----
    {
        const int ln = tid & 31, half = tid >> 5;
        for (int l = 0; l < 3; ++l) {
            for (int q = 0; q < 16; ++q) {
                const float* wr = w_h + (size_t)(l * NH + ln + 32 * half) * NH + 4 * q;
                float w0 = wr[0], w1v = wr[1], w2 = wr[2], w3 = wr[3];
                float* dst = tblH + (size_t)((l * 16 + q) * 16) * 64 + ln * 2 + half;
#pragma unroll
                for (int p = 0; p < 16; ++p) {
                    float s = 0.0f;
                    if (p & 1) s += w0;
                    if (p & 2) s += w1v;
                    if (p & 4) s += w2;
                    if (p & 8) s += w3;
                    dst[(size_t)p * 64] = s;
                }
            }
        }
        if (tid < 48) {
            const int o = tid >> 4, q = tid & 15;
            const float* wr = w_out + o * NH + 4 * q;
            float w0 = wr[0], w1v = wr[1], w2 = wr[2], w3 = wr[3];
#pragma unroll
            for (int p = 0; p < 16; ++p) {
                float s = 0.0f;
                if (p & 1) s += w0;
                if (p & 2) s += w1v;
                if (p & 4) s += w2;
                if (p & 8) s += w3;
                tblO[(q * 16 + p) * 4 + o] = s;
            }
        }
    }
    __syncthreads();   // the ONLY block barrier

    const int b = blockIdx.x * 2 + wid;

    // ---- per-lane weights / biases in registers ----
    float w1a[NS], w1b[NS];
#pragma unroll
    for (int s = 0; s < NS; ++s) {
        w1a[s] = w1[lane * NS + s];
        w1b[s] = w1[(lane + 32) * NS + s];
    }
    const float b1a = b1[lane], b1b = b1[lane + 32];
    float bha[3], bhb[3];
#pragma unroll
    for (int l = 0; l < 3; ++l) {
        bha[l] = b_h[l * NH + lane];
        bhb[l] = b_h[l * NH + lane + 32];
    }
    const float bo = (lane < NOUT) ? b_out[lane] : 0.0f;

    // ---- initial membranes ----
    float ma[NL], mb[NL];
    const float* h0 = hidden0 + (size_t)b * NT * NL * NH;
#pragma unroll
    for (int l = 0; l < NL; ++l) {
        ma[l] = h0[l * NH + lane];
        mb[l] = h0[l * NH + lane + 32];
    }

    // ---- x staging: register-prefetch chunk 0 ----
    const float* xb = x + (size_t)b * NT * NS;
    float* xw = xbuf + wid * XPC;
    float xs[14];
#pragma unroll
    for (int i = 0; i < 14; ++i) xs[i] = xb[i * 32 + lane];

    float* hout = out_hidden  + (size_t)b * NT * NL * NH;
    float* oout = out_outputs + (size_t)b * NT * NOUT;

    for (int c = 0; c < NT / CH; ++c) {
        __syncwarp();
#pragma unroll
        for (int i = 0; i < 14; ++i) xw[i * 32 + lane] = xs[i];
        __syncwarp();
        if (c + 1 < NT / CH) {
#pragma unroll
            for (int i = 0; i < 14; ++i) xs[i] = xb[(c + 1) * XPC + i * 32 + lane];
        }

        for (int tt = 0; tt < CH; ++tt) {
            const int t = c * CH + tt;
            const float* xt = xw + tt * NS;

            // input current
            float cx = b1a, cy = b1b;
#pragma unroll
            for (int s = 0; s < NS; ++s) {
                float xv = xt[s];
                cx = fmaf(xv, w1a[s], cx);
                cy = fmaf(xv, w1b[s], cy);
            }

            unsigned mlo3 = 0, mhi3 = 0;
#pragma unroll
            for (int l = 0; l < NL; ++l) {
                // membrane update: ((0.8*m) + cur) - reset ; spike = m_new > 1
                float nx = __fadd_rn(__fmul_rn(0.8f, ma[l]), cx);
                float ny = __fadd_rn(__fmul_rn(0.8f, mb[l]), cy);
                if (ma[l] > 1.0f) nx = __fadd_rn(nx, -1.0f);
                if (mb[l] > 1.0f) ny = __fadd_rn(ny, -1.0f);
                ma[l] = nx; mb[l] = ny;
                unsigned mlo = __ballot_sync(0xffffffffu, nx > 1.0f);
                unsigned mhi = __ballot_sync(0xffffffffu, ny > 1.0f);

                if (l < 3) {
                    float ax0 = 0.0f, ay0 = 0.0f, ax1 = 0.0f, ay1 = 0.0f;
#pragma unroll
                    for (int q = 0; q < 16; ++q) {
                        unsigned m   = (q < 8) ? mlo : mhi;
                        unsigned idx = (m >> ((4 * q) & 31)) & 15u;
                        const float2* e = reinterpret_cast<const float2*>(
                            tblH + (size_t)((l * 16 + q) * 16u + idx) * 64u) + lane;
                        float2 v = *e;                      // LDS.64, warp-uniform addr
                        if (q & 1) { ax1 += v.x; ay1 += v.y; }
                        else       { ax0 += v.x; ay0 += v.y; }
                    }
                    cx = (ax0 + ax1) + bha[l];
                    cy = (ay0 + ay1) + bhb[l];
                } else {
                    mlo3 = mlo; mhi3 = mhi;
                }
            }

            // output layer (3 lanes active)
            float oacc = bo;
#pragma unroll
            for (int q = 0; q < 16; ++q) {
                unsigned m   = (q < 8) ? mlo3 : mhi3;
                unsigned idx = (m >> ((4 * q) & 31)) & 15u;
                if (lane < NOUT) oacc += tblO[(q * 16 + idx) * 4 + lane];
            }
            if (lane < NOUT) oout[(size_t)t * NOUT + lane] = oacc;

            // hidden-state writeback (coalesced)
            float* hb = hout + (size_t)t * NL * NH;
#pragma unroll
            for (int l = 0; l < NL; ++l) {
                hb[l * NH + lane]      = ma[l];
                hb[l * NH + lane + 32] = mb[l];
            }
        }
    }
}

// x passthrough: third tuple element of the reference output
__global__ void copy_kernel(const float4* __restrict__ src,
                            float4* __restrict__ dst, int n4)
{
    int i = blockIdx.x * blockDim.x + threadIdx.x;
    if (i < n4) dst[i] = src[i];
}

extern "C" void kernel_launch(void* const* d_in, const int* in_sizes, int n_in,
                              void* d_out, int out_size)
{
    const float* x      = (const float*)d_in[0];
    const float* hidden = (const float*)d_in[1];
    // d_in[2] = prev_obs (unused by reference)
    const float* w1     = (const float*)d_in[3];
    const float* b1     = (const float*)d_in[4];
    const float* w_h    = (const float*)d_in[5];
    const float* b_h    = (const float*)d_in[6];
    const float* w_out  = (const float*)d_in[7];
    const float* b_out  = (const float*)d_in[8];

    float* out         = (float*)d_out;
    float* out_outputs = out;                                    // B*T*OUT
    float* out_hidden  = out_outputs + (size_t)NB * NT * NOUT;   // B*T*L*H
    float* out_x       = out_hidden + (size_t)NB * NT * NL * NH; // B*T*S

    cudaFuncSetAttribute(snn_kernel,
                         cudaFuncAttributeMaxDynamicSharedMemorySize, SMEM_BYTES);

    snn_kernel<<<NB / 2, 64, SMEM_BYTES>>>(x, hidden, w1, b1, w_h, b_h,
                                           w_out, b_out, out_outputs, out_hidden);

    const int n4 = (NB * NT * NS) / 4;
    copy_kernel<<<(n4 + 255) / 256, 256>>>((const float4*)x, (float4*)out_x, n4);
}

// round 4
// speedup vs baseline: 1.4138x; 1.4138x over previous
#include <cuda_runtime.h>

#define NB   256
#define NT   1024
#define NS   7
#define NH   64
#define NL   4
#define NOUT 3

#define CH   64
#define XPC  (CH * NS)                   // 448 floats per chunk
#define TBLH_FLOATS (3 * 16 * 16 * 64)   // 192 KB
#define TBLO_FLOATS (16 * 16 * 4)        // 4 KB
#define XS_FLOATS   (2 * XPC)            // 2 batches * 448
#define SMEM_FLOATS (TBLH_FLOATS + TBLO_FLOATS + XS_FLOATS)
#define SMEM_BYTES  (SMEM_FLOATS * 4 + 2 * 4 * 2 * 8)  // + mask ring

// 4-stage layer pipeline: warp `stage` of each batch processes timestep
// t = i - stage at pipeline interval i. Spike masks (64-bit, from ballots)
// flow stage->stage+1 through a parity-double-buffered smem ring; ONE
// __syncthreads per interval orders everything. Stage 0 additionally
// consumes mask3 (lag 4) for the output layer.
__global__ __launch_bounds__(256, 1)
void snn_kernel(const float* __restrict__ x,
                const float* __restrict__ hidden0,
                const float* __restrict__ w1,
                const float* __restrict__ b1,
                const float* __restrict__ w_h,
                const float* __restrict__ b_h,
                const float* __restrict__ w_out,
                const float* __restrict__ b_out,
                float* __restrict__ out_outputs,   // (B,T,OUT)
                float* __restrict__ out_hidden)    // (B,T,L,H)
{
    extern __shared__ float smem[];
    float* tblH = smem;                        // [3][16][16][64]
    float* tblO = smem + TBLH_FLOATS;          // [16][16][4]
    float* xbuf = tblO + TBLO_FLOATS;          // [2][XPC]
    uint2* masks = reinterpret_cast<uint2*>(smem + SMEM_FLOATS); // [2][4][2]

    const int tid   = threadIdx.x;
    const int lane  = tid & 31;
    const int wid   = tid >> 5;
    const int stage = wid & 3;
    const int bslot = wid >> 2;
    const int b     = blockIdx.x * 2 + bslot;

    // ---- build 4-bit subset-sum LUTs (256 threads cooperate) ----
    {
        const int ln = tid & 31, half = (tid >> 5) & 1, g = tid >> 6;
        for (int lq = g; lq < 48; lq += 4) {
            const int l = lq >> 4, q = lq & 15;
            const float* wr = w_h + (size_t)(l * NH + ln + 32 * half) * NH + 4 * q;
            float w0 = wr[0], w1v = wr[1], w2 = wr[2], w3 = wr[3];
            float* dst = tblH + (size_t)(lq * 16) * 64 + ln * 2 + half;
#pragma unroll
            for (int p = 0; p < 16; ++p) {
                float s = 0.0f;
                if (p & 1) s += w0;
                if (p & 2) s += w1v;
                if (p & 4) s += w2;
                if (p & 8) s += w3;
                dst[(size_t)p * 64] = s;
            }
        }
        if (tid < 48) {
            const int o = tid >> 4, q = tid & 15;
            const float* wr = w_out + o * NH + 4 * q;
            float w0 = wr[0], w1v = wr[1], w2 = wr[2], w3 = wr[3];
#pragma unroll
            for (int p = 0; p < 16; ++p) {
                float s = 0.0f;
                if (p & 1) s += w0;
                if (p & 2) s += w1v;
                if (p & 4) s += w2;
                if (p & 8) s += w3;
                tblO[(q * 16 + p) * 4 + o] = s;
            }
        }
    }
    __syncthreads();

    // ---- per-warp (stage) state ----
    float ma, mbv;   // membrane of this stage's layer, neurons (lane, lane+32)
    {
        const float* h0 = hidden0 + (size_t)b * NT * NL * NH + stage * NH;
        ma  = h0[lane];
        mbv = h0[lane + 32];
    }

    float w1a[NS], w1b[NS];
    float b1a = 0.f, b1b = 0.f, bo = 0.f, bha = 0.f, bhb = 0.f;
    float xs[14];
    const float* xb = x + (size_t)b * NT * NS;
    float* xw = xbuf + bslot * XPC;
    if (stage == 0) {
#pragma unroll
        for (int s = 0; s < NS; ++s) {
            w1a[s] = w1[lane * NS + s];
            w1b[s] = w1[(lane + 32) * NS + s];
        }
        b1a = b1[lane];
        b1b = b1[lane + 32];
        bo  = (lane < NOUT) ? b_out[lane] : 0.0f;
#pragma unroll
        for (int j = 0; j < 14; ++j) xs[j] = xb[j * 32 + lane];
    } else {
        bha = b_h[(stage - 1) * NH + lane];
        bhb = b_h[(stage - 1) * NH + lane + 32];
    }

    float* hout  = out_hidden  + (size_t)b * NT * NL * NH + stage * NH;
    float* oout  = out_outputs + (size_t)b * NT * NOUT;
    uint2* mslot = masks + bslot * 8;   // [edge 0..3][parity]

    for (int i = 0; i < NT + 4; ++i) {
        if (stage == 0) {
            if (i < NT) {
                if ((i & 63) == 0) {
#pragma unroll
                    for (int j = 0; j < 14; ++j) xw[j * 32 + lane] = xs[j];
                    __syncwarp();
                    const int c = i >> 6;
                    if (c + 1 < NT / CH) {
#pragma unroll
                        for (int j = 0; j < 14; ++j)
                            xs[j] = xb[(c + 1) * XPC + j * 32 + lane];
                    }
                }
                const float* xt = xw + (i & 63) * NS;
                float cx = b1a, cy = b1b;
#pragma unroll
                for (int s = 0; s < NS; ++s) {
                    float xv = xt[s];
                    cx = fmaf(xv, w1a[s], cx);
                    cy = fmaf(xv, w1b[s], cy);
                }
                float nx = __fadd_rn(__fmul_rn(0.8f, ma),  cx);
                float ny = __fadd_rn(__fmul_rn(0.8f, mbv), cy);
                if (ma  > 1.0f) nx = __fadd_rn(nx, -1.0f);
                if (mbv > 1.0f) ny = __fadd_rn(ny, -1.0f);
                ma = nx; mbv = ny;
                unsigned mlo = __ballot_sync(0xffffffffu, nx > 1.0f);
                unsigned mhi = __ballot_sync(0xffffffffu, ny > 1.0f);
                if (lane == 0) mslot[0 * 2 + (i & 1)] = make_uint2(mlo, mhi);
                float* hb = hout + (size_t)i * NL * NH;
                hb[lane]      = ma;
                hb[lane + 32] = mbv;
            }
            if (i >= 4) {
                const int tau = i - 4;
                uint2 m3 = mslot[3 * 2 + ((i - 1) & 1)];
                float oacc = bo;
#pragma unroll
                for (int q = 0; q < 16; ++q) {
                    unsigned m   = (q < 8) ? m3.x : m3.y;
                    unsigned idx = (m >> ((4 * q) & 31)) & 15u;
                    if (lane < NOUT) oacc += tblO[(q * 16 + idx) * 4 + lane];
                }
                if (lane < NOUT) oout[(size_t)tau * NOUT + lane] = oacc;
            }
        } else {
            const int t = i - stage;
            if (t >= 0 && t < NT) {
                uint2 mm = mslot[(stage - 1) * 2 + ((i - 1) & 1)];
                float ax0 = 0.f, ay0 = 0.f, ax1 = 0.f, ay1 = 0.f;
#pragma unroll
                for (int q = 0; q < 16; ++q) {
                    unsigned m   = (q < 8) ? mm.x : mm.y;
                    unsigned idx = (m >> ((4 * q) & 31)) & 15u;
                    const float2* e = reinterpret_cast<const float2*>(
                        tblH + (size_t)(((stage - 1) * 16 + q) * 16 + idx) * 64) + lane;
                    float2 v = *e;                       // LDS.64, warp-uniform addr
                    if (q & 1) { ax1 += v.x; ay1 += v.y; }
                    else       { ax0 += v.x; ay0 += v.y; }
                }
                float cx = (ax0 + ax1) + bha;
                float cy = (ay0 + ay1) + bhb;
                float nx = __fadd_rn(__fmul_rn(0.8f, ma),  cx);
                float ny = __fadd_rn(__fmul_rn(0.8f, mbv), cy);
                if (ma  > 1.0f) nx = __fadd_rn(nx, -1.0f);
                if (mbv > 1.0f) ny = __fadd_rn(ny, -1.0f);
                ma = nx; mbv = ny;
                unsigned mlo = __ballot_sync(0xffffffffu, nx > 1.0f);
                unsigned mhi = __ballot_sync(0xffffffffu, ny > 1.0f);
                if (lane == 0) mslot[stage * 2 + (i & 1)] = make_uint2(mlo, mhi);
                float* hb = hout + (size_t)t * NL * NH;
                hb[lane]      = ma;
                hb[lane + 32] = mbv;
            }
        }
        __syncthreads();   // orders mask publish -> next-interval consume
    }
}

// x passthrough: third tuple element of the reference output
__global__ void copy_kernel(const float4* __restrict__ src,
                            float4* __restrict__ dst, int n4)
{
    int i = blockIdx.x * blockDim.x + threadIdx.x;
    if (i < n4) dst[i] = src[i];
}

extern "C" void kernel_launch(void* const* d_in, const int* in_sizes, int n_in,
                              void* d_out, int out_size)
{
    const float* x      = (const float*)d_in[0];
    const float* hidden = (const float*)d_in[1];
    // d_in[2] = prev_obs (unused by reference)
    const float* w1     = (const float*)d_in[3];
    const float* b1     = (const float*)d_in[4];
    const float* w_h    = (const float*)d_in[5];
    const float* b_h    = (const float*)d_in[6];
    const float* w_out  = (const float*)d_in[7];
    const float* b_out  = (const float*)d_in[8];

    float* out         = (float*)d_out;
    float* out_outputs = out;                                    // B*T*OUT
    float* out_hidden  = out_outputs + (size_t)NB * NT * NOUT;   // B*T*L*H
    float* out_x       = out_hidden + (size_t)NB * NT * NL * NH; // B*T*S

    // copy FIRST so ncu (-s 5 -c 1) captures the SNN kernel this round
    const int n4 = (NB * NT * NS) / 4;
    copy_kernel<<<(n4 + 255) / 256, 256>>>((const float4*)x, (float4*)out_x, n4);

    cudaFuncSetAttribute(snn_kernel,
                         cudaFuncAttributeMaxDynamicSharedMemorySize, SMEM_BYTES);
    snn_kernel<<<NB / 2, 256, SMEM_BYTES>>>(x, hidden, w1, b1, w_h, b_h,
                                            w_out, b_out, out_outputs, out_hidden);
}

// round 5
// speedup vs baseline: 5.4616x; 3.8629x over previous
#include <cuda_runtime.h>

#define NB   256
#define NT   1024
#define NS   7
#define NH   64
#define NL   4
#define NOUT 3

#define UQ   8                            // timesteps per pipeline interval
#define NBLK (NT / UQ)                     // 128 timestep-blocks
#define CH   64                            // x-staging chunk (timesteps)
#define XPC  (CH * NS)                     // 448 floats
#define TBLH_FLOATS (3 * 16 * 16 * 64)     // 192 KB
#define TBLO_FLOATS (16 * 16 * 4)          // 4 KB
#define XS_FLOATS   (2 * XPC)
#define SMEM_FLOATS (TBLH_FLOATS + TBLO_FLOATS + XS_FLOATS)
#define SMEM_BYTES  (SMEM_FLOATS * 4 + 2 * 4 * 2 * UQ * 8)

// 4-stage layer pipeline, UQ=8 timesteps per interval.
// Warp `stage` of each batch processes timestep-block j = i - stage at
// interval i. Spike masks (64-bit) flow through a parity-double-buffered
// smem ring; ONE __syncthreads per interval (132 total vs 1028 steps).
// Within an interval all 8x16 LUT lookups are independent -> high ILP.
__global__ __launch_bounds__(256, 1)
void snn_kernel(const float* __restrict__ x,
                const float* __restrict__ hidden0,
                const float* __restrict__ w1,
                const float* __restrict__ b1,
                const float* __restrict__ w_h,
                const float* __restrict__ b_h,
                const float* __restrict__ w_out,
                const float* __restrict__ b_out,
                float* __restrict__ out_outputs,   // (B,T,OUT)
                float* __restrict__ out_hidden)    // (B,T,L,H)
{
    extern __shared__ float smem[];
    float* tblH = smem;                        // [3][16][16][64]
    float* tblO = smem + TBLH_FLOATS;          // [16][16][4]
    float* xbuf = tblO + TBLO_FLOATS;          // [2][XPC]
    // mask ring: [bslot][edge 0..3][parity][UQ]
    uint2 (*mring)[4][2][UQ] =
        reinterpret_cast<uint2 (*)[4][2][UQ]>(smem + SMEM_FLOATS);

    const int tid   = threadIdx.x;
    const int lane  = tid & 31;
    const int wid   = tid >> 5;
    const int stage = wid & 3;
    const int bslot = wid >> 2;
    const int b     = blockIdx.x * 2 + bslot;

    // ---- build 4-bit subset-sum LUTs (256 threads cooperate) ----
    {
        const int ln = tid & 31, half = (tid >> 5) & 1, g = tid >> 6;
        for (int lq = g; lq < 48; lq += 4) {
            const float* wr = w_h + (size_t)((lq >> 4) * NH + ln + 32 * half) * NH
                              + 4 * (lq & 15);
            float w0 = wr[0], w1v = wr[1], w2 = wr[2], w3 = wr[3];
            float* dst = tblH + (size_t)(lq * 16) * 64 + ln * 2 + half;
#pragma unroll
            for (int p = 0; p < 16; ++p) {
                float s = 0.0f;
                if (p & 1) s += w0;
                if (p & 2) s += w1v;
                if (p & 4) s += w2;
                if (p & 8) s += w3;
                dst[(size_t)p * 64] = s;
            }
        }
        if (tid < 48) {
            const int o = tid >> 4, q = tid & 15;
            const float* wr = w_out + o * NH + 4 * q;
            float w0 = wr[0], w1v = wr[1], w2 = wr[2], w3 = wr[3];
#pragma unroll
            for (int p = 0; p < 16; ++p) {
                float s = 0.0f;
                if (p & 1) s += w0;
                if (p & 2) s += w1v;
                if (p & 4) s += w2;
                if (p & 8) s += w3;
                tblO[(q * 16 + p) * 4 + o] = s;
            }
        }
    }
    __syncthreads();

    // ---- per-warp state: this stage's layer membranes ----
    float ma, mbv;
    {
        const float* h0 = hidden0 + (size_t)b * NT * NL * NH + stage * NH;
        ma  = h0[lane];
        mbv = h0[lane + 32];
    }

    float w1a[NS], w1b[NS];
    float b1a = 0.f, b1b = 0.f, bo = 0.f, bha = 0.f, bhb = 0.f;
    float xs[14];
    const float* xb = x + (size_t)b * NT * NS;
    float* xw = xbuf + bslot * XPC;
    const int otc = lane / 3;            // output: timestep-in-block
    const int oo  = lane - 3 * otc;      // output: channel
    if (stage == 0) {
#pragma unroll
        for (int s = 0; s < NS; ++s) {
            w1a[s] = w1[lane * NS + s];
            w1b[s] = w1[(lane + 32) * NS + s];
        }
        b1a = b1[lane];
        b1b = b1[lane + 32];
        bo  = (lane < 24) ? b_out[oo] : 0.0f;
#pragma unroll
        for (int j = 0; j < 14; ++j) xs[j] = xb[j * 32 + lane];
    } else {
        bha = b_h[(stage - 1) * NH + lane];
        bhb = b_h[(stage - 1) * NH + lane + 32];
    }

    float* hout = out_hidden  + (size_t)b * NT * NL * NH + stage * NH;
    float* oout = out_outputs + (size_t)b * NT * NOUT;

    for (int i = 0; i < NBLK + 4; ++i) {
        if (stage == 0) {
            if (i < NBLK) {
                if ((i & 7) == 0) {            // new 64-step x chunk
#pragma unroll
                    for (int j = 0; j < 14; ++j) xw[j * 32 + lane] = xs[j];
                    __syncwarp();
                    const int c = i >> 3;
                    if (c + 1 < NT / CH) {
#pragma unroll
                        for (int j = 0; j < 14; ++j)
                            xs[j] = xb[(c + 1) * XPC + j * 32 + lane];
                    }
                }
#pragma unroll
                for (int tt = 0; tt < UQ; ++tt) {
                    const int t = i * UQ + tt;
                    const float* xt = xw + (t & 63) * NS;
                    float cx = b1a, cy = b1b;
#pragma unroll
                    for (int s = 0; s < NS; ++s) {
                        float xv = xt[s];
                        cx = fmaf(xv, w1a[s], cx);
                        cy = fmaf(xv, w1b[s], cy);
                    }
                    float nx = __fadd_rn(__fmul_rn(0.8f, ma),  cx);
                    float ny = __fadd_rn(__fmul_rn(0.8f, mbv), cy);
                    if (ma  > 1.0f) nx = __fadd_rn(nx, -1.0f);
                    if (mbv > 1.0f) ny = __fadd_rn(ny, -1.0f);
                    ma = nx; mbv = ny;
                    unsigned mlo = __ballot_sync(0xffffffffu, nx > 1.0f);
                    unsigned mhi = __ballot_sync(0xffffffffu, ny > 1.0f);
                    if (lane == 0) mring[bslot][0][i & 1][tt] = make_uint2(mlo, mhi);
                    float* hb = hout + (size_t)t * NL * NH;
                    hb[lane]      = ma;
                    hb[lane + 32] = mbv;
                }
            }
            if (i >= 4) {                      // output layer: block j2 = i-4
                const int j2 = i - 4;
                uint2 m3 = make_uint2(0u, 0u);
                if (lane < 24) m3 = mring[bslot][3][(i - 1) & 1][otc];
                float oacc = bo;
#pragma unroll
                for (int q = 0; q < 16; ++q) {
                    unsigned m   = (q < 8) ? m3.x : m3.y;
                    unsigned idx = (m >> ((4 * q) & 31)) & 15u;
                    oacc += tblO[(q * 16 + idx) * 4 + oo];
                }
                if (lane < 24) oout[(size_t)j2 * (UQ * NOUT) + lane] = oacc;
            }
        } else {
            const int jj = i - stage;
            if (jj >= 0 && jj < NBLK) {
                const int par = (i - 1) & 1;
                uint2 mm[UQ];
#pragma unroll
                for (int tt = 0; tt < UQ; ++tt)
                    mm[tt] = mring[bslot][stage - 1][par][tt];
                const float* tbl = tblH + (size_t)(stage - 1) * (16 * 16 * 64);
#pragma unroll
                for (int tt = 0; tt < UQ; ++tt) {
                    float ax0 = 0.f, ay0 = 0.f, ax1 = 0.f, ay1 = 0.f;
#pragma unroll
                    for (int q = 0; q < 16; ++q) {
                        unsigned m   = (q < 8) ? mm[tt].x : mm[tt].y;
                        unsigned idx = (m >> ((4 * q) & 31)) & 15u;
                        const float2* e = reinterpret_cast<const float2*>(
                            tbl + (size_t)((q * 16 + idx) * 64)) + lane;
                        float2 v = *e;               // LDS.64, warp-uniform
                        if (q & 1) { ax1 += v.x; ay1 += v.y; }
                        else       { ax0 += v.x; ay0 += v.y; }
                    }
                    float cx = (ax0 + ax1) + bha;
                    float cy = (ay0 + ay1) + bhb;
                    float nx = __fadd_rn(__fmul_rn(0.8f, ma),  cx);
                    float ny = __fadd_rn(__fmul_rn(0.8f, mbv), cy);
                    if (ma  > 1.0f) nx = __fadd_rn(nx, -1.0f);
                    if (mbv > 1.0f) ny = __fadd_rn(ny, -1.0f);
                    ma = nx; mbv = ny;
                    unsigned mlo = __ballot_sync(0xffffffffu, nx > 1.0f);
                    unsigned mhi = __ballot_sync(0xffffffffu, ny > 1.0f);
                    if (lane == 0)
                        mring[bslot][stage][i & 1][tt] = make_uint2(mlo, mhi);
                    const int t = jj * UQ + tt;
                    float* hb = hout + (size_t)t * NL * NH;
                    hb[lane]      = ma;
                    hb[lane + 32] = mbv;
                }
            }
        }
        __syncthreads();   // orders mask publish -> next-interval consume
    }
}

// x passthrough: third tuple element of the reference output
__global__ void copy_kernel(const float4* __restrict__ src,
                            float4* __restrict__ dst, int n4)
{
    int i = blockIdx.x * blockDim.x + threadIdx.x;
    if (i < n4) dst[i] = src[i];
}

extern "C" void kernel_launch(void* const* d_in, const int* in_sizes, int n_in,
                              void* d_out, int out_size)
{
    const float* x      = (const float*)d_in[0];
    const float* hidden = (const float*)d_in[1];
    // d_in[2] = prev_obs (unused by reference)
    const float* w1     = (const float*)d_in[3];
    const float* b1     = (const float*)d_in[4];
    const float* w_h    = (const float*)d_in[5];
    const float* b_h    = (const float*)d_in[6];
    const float* w_out  = (const float*)d_in[7];
    const float* b_out  = (const float*)d_in[8];

    float* out         = (float*)d_out;
    float* out_outputs = out;                                    // B*T*OUT
    float* out_hidden  = out_outputs + (size_t)NB * NT * NOUT;   // B*T*L*H
    float* out_x       = out_hidden + (size_t)NB * NT * NL * NH; // B*T*S

    // copy FIRST so ncu (-s 5 -c 1) captures the SNN kernel
    const int n4 = (NB * NT * NS) / 4;
    copy_kernel<<<(n4 + 255) / 256, 256>>>((const float4*)x, (float4*)out_x, n4);

    cudaFuncSetAttribute(snn_kernel,
                         cudaFuncAttributeMaxDynamicSharedMemorySize, SMEM_BYTES);
    snn_kernel<<<NB / 2, 256, SMEM_BYTES>>>(x, hidden, w1, b1, w_h, b_h,
                                            w_out, b_out, out_outputs, out_hidden);
}

// round 6
// speedup vs baseline: 5.8351x; 1.0684x over previous
#include <cuda_runtime.h>

#define NB   256
#define NT   1024
#define NS   7
#define NH   64
#define NL   4
#define NOUT 3

#define UQ   8                             // timesteps per pipeline interval
#define NBLK (NT / UQ)                     // 128 timestep-blocks
#define CH   64                            // x-staging chunk (timesteps)
#define XPC  (CH * NS)                     // 448 floats
#define TBLH_FLOATS (3 * 16 * 16 * 64)     // 192 KB
#define TBLO_FLOATS (16 * 16 * 4)          // 4 KB
#define XS_FLOATS   (2 * XPC)
#define SMEM_FLOATS (TBLH_FLOATS + TBLO_FLOATS + XS_FLOATS)
#define SMEM_BYTES  (SMEM_FLOATS * 4 + 2 * 4 * 2 * UQ * 8)

// packed fp32x2 add — same form as ptx_helpers.cuh ADD_F32X2 (no "+l")
#define ADDX2(out, a, b) \
    asm("add.rn.f32x2 %0, %1, %2;" : "=l"(out) : "l"(a), "l"(b))

typedef unsigned long long ull;

// Neuron ownership: lane owns neurons (2*lane, 2*lane+1).
// Ballot A: bit lane = spike of neuron 2*lane (even neurons)
// Ballot B: bit lane = spike of neuron 2*lane+1 (odd neurons)
// Input grouping for LUT: group g in [0,8): nibble g of maskA
//   -> input neurons {8g, 8g+2, 8g+4, 8g+6}
// group g in [8,16): nibble (g-8) of maskB -> {8(g-8)+1, +3, +5, +7}
__device__ __forceinline__ int in_neuron(int g, int i) {
    return (g < 8) ? (8 * g + 2 * i) : (8 * (g - 8) + 2 * i + 1);
}

__global__ __launch_bounds__(256, 1)
void snn_kernel(const float* __restrict__ x,
                const float* __restrict__ hidden0,
                const float* __restrict__ w1,
                const float* __restrict__ b1,
                const float* __restrict__ w_h,
                const float* __restrict__ b_h,
                const float* __restrict__ w_out,
                const float* __restrict__ b_out,
                float* __restrict__ out_outputs,   // (B,T,OUT)
                float* __restrict__ out_hidden)    // (B,T,L,H)
{
    extern __shared__ float smem[];
    float* tblH = smem;                        // [3*16][16][64]
    float* tblO = smem + TBLH_FLOATS;          // [16][16][4]
    float* xbuf = tblO + TBLO_FLOATS;          // [2][XPC]
    uint2 (*mring)[4][2][UQ] =
        reinterpret_cast<uint2 (*)[4][2][UQ]>(smem + SMEM_FLOATS);

    const int tid   = threadIdx.x;
    const int lane  = tid & 31;
    const int wid   = tid >> 5;
    const int stage = wid & 3;
    const int bslot = wid >> 2;
    const int b     = blockIdx.x * 2 + bslot;

    // ---- build LUTs (remapped grouping, paired-output float2 rows) ----
    {
        const int ln = tid & 31;        // output pair (2ln, 2ln+1)
        const int w  = tid >> 5;        // 8 warps stripe the 48 (l,g) slices
        for (int lg = w; lg < 48; lg += 8) {
            const int l = lg >> 4, g = lg & 15;
            float wa[4], wb[4];
#pragma unroll
            for (int i = 0; i < 4; ++i) {
                const int in = in_neuron(g, i);
                wa[i] = w_h[(size_t)(l * NH + 2 * ln)     * NH + in];
                wb[i] = w_h[(size_t)(l * NH + 2 * ln + 1) * NH + in];
            }
            float* dst = tblH + (size_t)(lg * 16) * 64 + 2 * ln;
#pragma unroll
            for (int p = 0; p < 16; ++p) {
                float sa = 0.f, sb = 0.f;
                if (p & 1) { sa += wa[0]; sb += wb[0]; }
                if (p & 2) { sa += wa[1]; sb += wb[1]; }
                if (p & 4) { sa += wa[2]; sb += wb[2]; }
                if (p & 8) { sa += wa[3]; sb += wb[3]; }
                *reinterpret_cast<float2*>(dst + (size_t)p * 64) =
                    make_float2(sa, sb);
            }
        }
        if (tid < 48) {
            const int o = tid >> 4, g = tid & 15;
            float wo[4];
#pragma unroll
            for (int i = 0; i < 4; ++i)
                wo[i] = w_out[o * NH + in_neuron(g, i)];
#pragma unroll
            for (int p = 0; p < 16; ++p) {
                float s = 0.f;
                if (p & 1) s += wo[0];
                if (p & 2) s += wo[1];
                if (p & 4) s += wo[2];
                if (p & 8) s += wo[3];
                tblO[(g * 16 + p) * 4 + o] = s;
            }
        }
    }
    __syncthreads();

    // ---- per-warp state: this stage's layer membranes (neurons 2lane,2lane+1)
    float ma, mbv;
    {
        const float* h0 = hidden0 + (size_t)b * NT * NL * NH + stage * NH;
        float2 m0 = *reinterpret_cast<const float2*>(h0 + 2 * lane);
        ma = m0.x; mbv = m0.y;
    }

    float w1a[NS], w1b[NS];
    float b1a = 0.f, b1b = 0.f, bo = 0.f, bha = 0.f, bhb = 0.f;
    float xs[14];
    const float* xb = x + (size_t)b * NT * NS;
    float* xw = xbuf + bslot * XPC;
    const int otc = lane / 3;            // output: timestep-in-block
    const int oo  = lane - 3 * otc;      // output: channel
    if (stage == 0) {
#pragma unroll
        for (int s = 0; s < NS; ++s) {
            w1a[s] = w1[(2 * lane)     * NS + s];
            w1b[s] = w1[(2 * lane + 1) * NS + s];
        }
        b1a = b1[2 * lane];
        b1b = b1[2 * lane + 1];
        bo  = (lane < 24) ? b_out[oo] : 0.0f;
#pragma unroll
        for (int j = 0; j < 14; ++j) xs[j] = xb[j * 32 + lane];
    } else {
        bha = b_h[(stage - 1) * NH + 2 * lane];
        bhb = b_h[(stage - 1) * NH + 2 * lane + 1];
    }

    float* hout = out_hidden  + (size_t)b * NT * NL * NH + stage * NH;
    float* oout = out_outputs + (size_t)b * NT * NOUT;
    // byte base of this stage's LUT slice, pre-offset by lane pair
    const char* tb = reinterpret_cast<const char*>(
        tblH + (size_t)(stage > 0 ? (stage - 1) : 0) * (16 * 16 * 64)) + lane * 8;

    for (int i = 0; i < NBLK + 4; ++i) {
        if (stage == 0) {
            if (i < NBLK) {
                if ((i & 7) == 0) {            // new 64-step x chunk
#pragma unroll
                    for (int j = 0; j < 14; ++j) xw[j * 32 + lane] = xs[j];
                    __syncwarp();
                    const int c = i >> 3;
                    if (c + 1 < NT / CH) {
#pragma unroll
                        for (int j = 0; j < 14; ++j)
                            xs[j] = xb[(c + 1) * XPC + j * 32 + lane];
                    }
                }
#pragma unroll
                for (int tt = 0; tt < UQ; ++tt) {
                    const int t = i * UQ + tt;
                    const float* xt = xw + (t & 63) * NS;
                    float cx = b1a, cy = b1b;
#pragma unroll
                    for (int s = 0; s < NS; ++s) {
                        float xv = xt[s];
                        cx = fmaf(xv, w1a[s], cx);
                        cy = fmaf(xv, w1b[s], cy);
                    }
                    float nx = __fadd_rn(__fmul_rn(0.8f, ma),  cx);
                    float ny = __fadd_rn(__fmul_rn(0.8f, mbv), cy);
                    if (ma  > 1.0f) nx = __fadd_rn(nx, -1.0f);
                    if (mbv > 1.0f) ny = __fadd_rn(ny, -1.0f);
                    ma = nx; mbv = ny;
                    unsigned mA = __ballot_sync(0xffffffffu, nx > 1.0f);
                    unsigned mB = __ballot_sync(0xffffffffu, ny > 1.0f);
                    if (lane == 0) mring[bslot][0][i & 1][tt] = make_uint2(mA, mB);
                    *reinterpret_cast<float2*>(
                        hout + (size_t)t * NL * NH + 2 * lane) = make_float2(ma, mbv);
                }
            }
            if (i >= 4) {                      // output layer: block j2 = i-4
                const int j2 = i - 4;
                uint2 m3 = make_uint2(0u, 0u);
                if (lane < 24) m3 = mring[bslot][3][(i - 1) & 1][otc];
                const unsigned eA = m3.x & 0x0F0F0F0Fu, oA = (m3.x >> 4) & 0x0F0F0F0Fu;
                const unsigned eB = m3.y & 0x0F0F0F0Fu, oB = (m3.y >> 4) & 0x0F0F0F0Fu;
                float oacc = bo;
#pragma unroll
                for (int g = 0; g < 16; ++g) {
                    unsigned src = (g < 8) ? ((g & 1) ? oA : eA)
                                           : ((g & 1) ? oB : eB);
                    unsigned idx = __byte_perm(src, 0, 0x4440 | ((g >> 1) & 3));
                    oacc += tblO[(g * 16 + idx) * 4 + oo];
                }
                if (lane < 24) oout[(size_t)j2 * (UQ * NOUT) + lane] = oacc;
            }
        } else {
            const int jj = i - stage;
            if (jj >= 0 && jj < NBLK) {
                const int par = (i - 1) & 1;
                uint2 mm[UQ];
#pragma unroll
                for (int tt = 0; tt < UQ; ++tt)
                    mm[tt] = mring[bslot][stage - 1][par][tt];
#pragma unroll
                for (int tt = 0; tt < UQ; ++tt) {
                    const unsigned eA = mm[tt].x & 0x0F0F0F0Fu;
                    const unsigned oA = (mm[tt].x >> 4) & 0x0F0F0F0Fu;
                    const unsigned eB = mm[tt].y & 0x0F0F0F0Fu;
                    const unsigned oB = (mm[tt].y >> 4) & 0x0F0F0F0Fu;
                    ull a0 = 0ull, a1 = 0ull;
#pragma unroll
                    for (int g = 0; g < 16; ++g) {
                        unsigned src = (g < 8) ? ((g & 1) ? oA : eA)
                                               : ((g & 1) ? oB : eB);
                        unsigned idx = __byte_perm(src, 0, 0x4440 | ((g >> 1) & 3));
                        ull v = *reinterpret_cast<const ull*>(
                            tb + ((size_t)g << 12) + ((size_t)idx << 8));
                        if (g & 1) { ull r; ADDX2(r, a1, v); a1 = r; }
                        else       { ull r; ADDX2(r, a0, v); a0 = r; }
                    }
                    ull at; ADDX2(at, a0, a1);
                    float2 av = *reinterpret_cast<float2*>(&at);
                    float cx = av.x + bha;
                    float cy = av.y + bhb;
                    float nx = __fadd_rn(__fmul_rn(0.8f, ma),  cx);
                    float ny = __fadd_rn(__fmul_rn(0.8f, mbv), cy);
                    if (ma  > 1.0f) nx = __fadd_rn(nx, -1.0f);
                    if (mbv > 1.0f) ny = __fadd_rn(ny, -1.0f);
                    ma = nx; mbv = ny;
                    unsigned mA = __ballot_sync(0xffffffffu, nx > 1.0f);
                    unsigned mB = __ballot_sync(0xffffffffu, ny > 1.0f);
                    if (lane == 0)
                        mring[bslot][stage][i & 1][tt] = make_uint2(mA, mB);
                    const int t = jj * UQ + tt;
                    *reinterpret_cast<float2*>(
                        hout + (size_t)t * NL * NH + 2 * lane) = make_float2(ma, mbv);
                }
            }
        }
        __syncthreads();   // orders mask publish -> next-interval consume
    }
}

// x passthrough: third tuple element of the reference output
__global__ void copy_kernel(const float4* __restrict__ src,
                            float4* __restrict__ dst, int n4)
{
    int i = blockIdx.x * blockDim.x + threadIdx.x;
    if (i < n4) dst[i] = src[i];
}

extern "C" void kernel_launch(void* const* d_in, const int* in_sizes, int n_in,
                              void* d_out, int out_size)
{
    const float* x      = (const float*)d_in[0];
    const float* hidden = (const float*)d_in[1];
    // d_in[2] = prev_obs (unused by reference)
    const float* w1     = (const float*)d_in[3];
    const float* b1     = (const float*)d_in[4];
    const float* w_h    = (const float*)d_in[5];
    const float* b_h    = (const float*)d_in[6];
    const float* w_out  = (const float*)d_in[7];
    const float* b_out  = (const float*)d_in[8];

    float* out         = (float*)d_out;
    float* out_outputs = out;                                    // B*T*OUT
    float* out_hidden  = out_outputs + (size_t)NB * NT * NOUT;   // B*T*L*H
    float* out_x       = out_hidden + (size_t)NB * NT * NL * NH; // B*T*S

    // copy FIRST so ncu (-s 5 -c 1) captures the SNN kernel
    const int n4 = (NB * NT * NS) / 4;
    copy_kernel<<<(n4 + 255) / 256, 256>>>((const float4*)x, (float4*)out_x, n4);

    cudaFuncSetAttribute(snn_kernel,
                         cudaFuncAttributeMaxDynamicSharedMemorySize, SMEM_BYTES);
    snn_kernel<<<NB / 2, 256, SMEM_BYTES>>>(x, hidden, w1, b1, w_h, b_h,
                                            w_out, b_out, out_outputs, out_hidden);
}